// round 5
// baseline (speedup 1.0000x reference)
#include <cuda_runtime.h>
#include <cuda_bf16.h>
#include <cstdint>
#include <cstring>

#define B_    256
#define IND   2048
#define D_    128
#define KQ    65536
#define LD_   65569              /* 1 + K + S1 + S2 */
#define INV_T (1.0f/0.07f)
#define SPLITK 8

// ---------------- device scratch (no allocation allowed) -------------------
__device__ __align__(16) float g_pq[SPLITK * B_ * D_];
__device__ __align__(16) float g_pk[SPLITK * B_ * D_];
__device__ __align__(16) float g_outq[B_ * D_];    // normalized out_q [256][128]
__device__ __align__(16) float g_outqT[D_ * B_];   // transposed      [128][256]
__device__ int g_hard[B_ * 32];

// packed f32x2 FMA (PTX-only on sm_103a; doubles fp32 MAC rate)
__device__ __forceinline__ float2 ffma2(float2 a, float2 b, float2 c) {
    unsigned long long ua, ub, uc, ud;
    memcpy(&ua, &a, 8); memcpy(&ub, &b, 8); memcpy(&uc, &c, 8);
    asm("fma.rn.f32x2 %0, %1, %2, %3;" : "=l"(ud) : "l"(ua), "l"(ub), "l"(uc));
    float2 r; memcpy(&r, &ud, 8);
    return r;
}

// ---------------- k1: encoder GEMMs, split-K=8 into partial buffers --------
__global__ void k1_gemm(const float* __restrict__ q, const float* __restrict__ kk,
                        const float* __restrict__ Wq, const float* __restrict__ Wk) {
    __shared__ float qs[16][32];
    __shared__ float ks[16][32];
    const float C0 = 0.999f;
    const float C1 = 1.0f - 0.999f;
    int t = threadIdx.x;
    int c = t & 127, h = t >> 7;          // h in {0,1}: 8 rows each
    int rb = blockIdx.x * 16;
    int k0 = blockIdx.y * (IND / SPLITK); // 256-wide K slice

    float aq[8], ak[8];
    #pragma unroll
    for (int j = 0; j < 8; j++) { aq[j] = 0.f; ak[j] = 0.f; }

    for (int kc = 0; kc < IND / SPLITK; kc += 32) {
        __syncthreads();
        #pragma unroll
        for (int e = 0; e < 2; e++) {
            int id = t + e * 256;
            int r = id >> 5, i = id & 31;
            qs[r][i] = q [(size_t)(rb + r) * IND + k0 + kc + i];
            ks[r][i] = kk[(size_t)(rb + r) * IND + k0 + kc + i];
        }
        __syncthreads();
        #pragma unroll
        for (int u0 = 0; u0 < 32; u0 += 8) {
            float wq[8], wm[8];
            #pragma unroll
            for (int u = 0; u < 8; u++) {
                float a = Wq[(size_t)(k0 + kc + u0 + u) * D_ + c];
                float b = Wk[(size_t)(k0 + kc + u0 + u) * D_ + c];
                wq[u] = a;
                wm[u] = C0 * b + C1 * a;
            }
            #pragma unroll
            for (int u = 0; u < 8; u++)
                #pragma unroll
                for (int j = 0; j < 8; j++) {
                    aq[j] = fmaf(qs[h * 8 + j][u0 + u], wq[u], aq[j]);
                    ak[j] = fmaf(ks[h * 8 + j][u0 + u], wm[u], ak[j]);
                }
        }
    }
    int sk = blockIdx.y;
    #pragma unroll
    for (int j = 0; j < 8; j++) {
        int r = rb + h * 8 + j;
        g_pq[((size_t)sk * B_ + r) * D_ + c] = aq[j];
        g_pk[((size_t)sk * B_ + r) * D_ + c] = ak[j];
    }
}

// ---------------- k1b: reduce partials, normalize, pos logit ---------------
__global__ void k1b_norm(float* __restrict__ out) {
    int t = threadIdx.x, lane = t & 31, w = t >> 5;
    int rb = blockIdx.x * 32;
    for (int rr = 0; rr < 4; rr++) {
        int r = rb + rr * 8 + w;
        float4 q4 = make_float4(0.f, 0.f, 0.f, 0.f);
        float4 k4 = make_float4(0.f, 0.f, 0.f, 0.f);
        #pragma unroll
        for (int s = 0; s < SPLITK; s++) {
            float4 a = *(const float4*)&g_pq[((size_t)s * B_ + r) * D_ + lane * 4];
            float4 b = *(const float4*)&g_pk[((size_t)s * B_ + r) * D_ + lane * 4];
            q4.x += a.x; q4.y += a.y; q4.z += a.z; q4.w += a.w;
            k4.x += b.x; k4.y += b.y; k4.z += b.z; k4.w += b.w;
        }
        float s1 = q4.x*q4.x + q4.y*q4.y + q4.z*q4.z + q4.w*q4.w;
        float s2 = k4.x*k4.x + k4.y*k4.y + k4.z*k4.z + k4.w*k4.w;
        float s3 = q4.x*k4.x + q4.y*k4.y + q4.z*k4.z + q4.w*k4.w;
        #pragma unroll
        for (int o = 16; o; o >>= 1) {
            s1 += __shfl_xor_sync(0xffffffffu, s1, o);
            s2 += __shfl_xor_sync(0xffffffffu, s2, o);
            s3 += __shfl_xor_sync(0xffffffffu, s3, o);
        }
        float invq = 1.f / fmaxf(sqrtf(s1), 1e-12f);
        float invk = 1.f / fmaxf(sqrtf(s2), 1e-12f);
        float4 nq;
        nq.x = q4.x * invq; nq.y = q4.y * invq; nq.z = q4.z * invq; nq.w = q4.w * invq;
        *(float4*)&g_outq[(size_t)r * D_ + lane * 4] = nq;
        g_outqT[(lane * 4 + 0) * B_ + r] = nq.x;
        g_outqT[(lane * 4 + 1) * B_ + r] = nq.y;
        g_outqT[(lane * 4 + 2) * B_ + r] = nq.z;
        g_outqT[(lane * 4 + 3) * B_ + r] = nq.w;
        if (lane == 0) out[(size_t)r * LD_] = s3 * invq * invk * INV_T;
    }
}

// ---------------- k2: main GEMM 256 x 65536 x 128, packed f32x2 ------------
#define AST 256
#define BST 65
#define K2_SMEM ((128*AST + 128*BST) * 4)

__global__ void k2_gemm(const float* __restrict__ queue, float* __restrict__ out) {
    extern __shared__ __align__(16) float sm[];
    float* As = sm;                 // [k][m] 128 x 256
    float* Bs = sm + 128 * AST;     // [k][n] 128 x 65 (pad)
    int t = threadIdx.x, lane = t & 31, w = t >> 5;
    int n0 = w * 8;

    // load A once (g_outqT is [k][m] already; contiguous LDG.128, conflict-free STS.128)
    #pragma unroll
    for (int e = 0; e < 32; e++) {
        int idx4 = t + e * 256;
        int kk2 = idx4 >> 6;
        int m4  = (idx4 & 63) * 4;
        *(float4*)(As + kk2 * AST + m4) = *(const float4*)(g_outqT + kk2 * B_ + m4);
    }

    for (int ci = blockIdx.x; ci < KQ / 64; ci += gridDim.x) {
        int nb = ci * 64;
        __syncthreads();   // As visible (1st iter) / Bs free (later iters)
        #pragma unroll
        for (int e = 0; e < 8; e++) {
            int idx4 = t + e * 256;
            int n  = idx4 >> 5;
            int k4 = (idx4 & 31) * 4;
            float4 v = *(const float4*)(queue + (size_t)(nb + n) * D_ + k4);
            Bs[(k4 + 0) * BST + n] = v.x;
            Bs[(k4 + 1) * BST + n] = v.y;
            Bs[(k4 + 2) * BST + n] = v.z;
            Bs[(k4 + 3) * BST + n] = v.w;
        }
        __syncthreads();

        float2 acc[2][2][8];
        #pragma unroll
        for (int a1 = 0; a1 < 2; a1++)
            #pragma unroll
            for (int a2 = 0; a2 < 2; a2++)
                #pragma unroll
                for (int a3 = 0; a3 < 8; a3++) { acc[a1][a2][a3].x = 0.f; acc[a1][a2][a3].y = 0.f; }

        #pragma unroll 4
        for (int k = 0; k < 128; k++) {
            float4 a0 = *(const float4*)(As + k * AST + lane * 4);
            float4 a1 = *(const float4*)(As + k * AST + 128 + lane * 4);
            float2 p00 = make_float2(a0.x, a0.y), p01 = make_float2(a0.z, a0.w);
            float2 p10 = make_float2(a1.x, a1.y), p11 = make_float2(a1.z, a1.w);
            const float* brow = Bs + k * BST + n0;
            #pragma unroll
            for (int c2 = 0; c2 < 8; c2++) {
                float b = brow[c2];
                float2 bb = make_float2(b, b);
                acc[0][0][c2] = ffma2(p00, bb, acc[0][0][c2]);
                acc[0][1][c2] = ffma2(p01, bb, acc[0][1][c2]);
                acc[1][0][c2] = ffma2(p10, bb, acc[1][0][c2]);
                acc[1][1][c2] = ffma2(p11, bb, acc[1][1][c2]);
            }
        }

        #pragma unroll
        for (int qd = 0; qd < 2; qd++)
            #pragma unroll
            for (int p = 0; p < 2; p++) {
                int r0 = qd * 128 + lane * 4 + p * 2;
                size_t b0 = (size_t)r0 * LD_ + 1 + nb + n0;
                size_t b1 = b0 + LD_;
                #pragma unroll
                for (int c2 = 0; c2 < 8; c2++) {
                    out[b0 + c2] = acc[qd][p][c2].x * INV_T;
                    out[b1 + c2] = acc[qd][p][c2].y * INV_T;
                }
            }
    }
}

// ---------------- k3: exact top-32 per row (hist threshold + argmax) -------
#define NBIN 8192
#define CAP  4096
#define K3_SMEM (NBIN * 4 + CAP * 8)

__global__ void k3_topk(const float* __restrict__ out) {
    extern __shared__ __align__(16) unsigned sm3[];
    unsigned* hist = sm3;
    unsigned long long* cand = (unsigned long long*)(sm3 + NBIN);
    __shared__ unsigned scnt[256];
    __shared__ unsigned s_tbin, s_cc;
    __shared__ unsigned long long s_red[8];
    int t = threadIdx.x, lane = t & 31, w = t >> 5;
    int r = blockIdx.x;
    const float* row = out + (size_t)r * LD_ + 1;

    for (int i = t; i < NBIN; i += 256) hist[i] = 0;
    if (t == 0) s_cc = 0;
    __syncthreads();

    for (int j = t; j < KQ; j += 256) {
        unsigned u = __float_as_uint(row[j]);
        unsigned fk = (u >> 31) ? ~u : (u | 0x80000000u);
        atomicAdd(&hist[fk >> 19], 1u);
    }
    __syncthreads();

    unsigned loc = 0;
    #pragma unroll 4
    for (int i = 0; i < 32; i++) loc += hist[t * 32 + i];
    scnt[t] = loc;
    __syncthreads();

    if (t == 0) {
        unsigned cum = 0; int seg = 255;
        for (; seg >= 0; seg--) { cum += scnt[seg]; if (cum >= 32) break; }
        unsigned cum2 = cum - scnt[seg];
        int tb = seg * 32;
        for (int i = 31; i >= 0; i--) {
            cum2 += hist[seg * 32 + i];
            if (cum2 >= 32) { tb = seg * 32 + i; break; }
        }
        s_tbin = (unsigned)tb;
    }
    __syncthreads();

    unsigned tb = s_tbin;
    for (int j = t; j < KQ; j += 256) {
        unsigned u = __float_as_uint(row[j]);
        unsigned fk = (u >> 31) ? ~u : (u | 0x80000000u);
        if ((fk >> 19) >= tb) {
            unsigned pos = atomicAdd(&s_cc, 1u);
            if (pos < CAP)
                cand[pos] = ((unsigned long long)fk << 32) | (unsigned)(~(unsigned)j);
        }
    }
    __syncthreads();
    int n = (int)min(s_cc, (unsigned)CAP);

    for (int sel = 0; sel < 32; sel++) {
        unsigned long long best = 0ull;
        for (int j = t; j < n; j += 256) {
            unsigned long long v = cand[j];
            if (v > best) best = v;
        }
        #pragma unroll
        for (int o = 16; o; o >>= 1) {
            unsigned long long oth = __shfl_xor_sync(0xffffffffu, best, o);
            if (oth > best) best = oth;
        }
        if (lane == 0) s_red[w] = best;
        __syncthreads();
        if (t == 0) {
            best = s_red[0];
            #pragma unroll
            for (int i = 1; i < 8; i++) if (s_red[i] > best) best = s_red[i];
            s_red[0] = best;
            g_hard[r * 32 + sel] = (int)(~(unsigned)(best & 0xFFFFFFFFull));
        }
        __syncthreads();
        best = s_red[0];
        for (int j = t; j < n; j += 256)
            if (cand[j] == best) cand[j] = 0ull;
        __syncthreads();
    }
}

// ---------------- k4: mixed hard-negative logits ---------------------------
__global__ void k4_mix(const float* __restrict__ queue, const float* __restrict__ alpha,
                       const float* __restrict__ beta, const int* __restrict__ i1a,
                       const int* __restrict__ i1b, const int* __restrict__ i2,
                       float* __restrict__ out) {
    __shared__ float qsh[D_];
    __shared__ int hsh[32];
    int t = threadIdx.x, lane = t & 31, w = t >> 5;
    int r = blockIdx.x;
    if (t < D_) qsh[t] = g_outq[(size_t)r * D_ + t];
    if (t < 32) hsh[t] = g_hard[r * 32 + t];
    __syncthreads();
    float4 q4 = *(float4*)&qsh[lane * 4];

    #pragma unroll
    for (int e = 0; e < 2; e++) {
        int s = w * 2 + e;
        // type 1
        {
            int g1 = hsh[i1a[r * 16 + s]];
            int g2 = hsh[i1b[r * 16 + s]];
            float a = alpha[r * 16 + s];
            float4 n1 = *(const float4*)(queue + (size_t)g1 * D_ + lane * 4);
            float4 n2 = *(const float4*)(queue + (size_t)g2 * D_ + lane * 4);
            float4 v;
            v.x = a * n1.x + (1.f - a) * n2.x;
            v.y = a * n1.y + (1.f - a) * n2.y;
            v.z = a * n1.z + (1.f - a) * n2.z;
            v.w = a * n1.w + (1.f - a) * n2.w;
            float ss = v.x*v.x + v.y*v.y + v.z*v.z + v.w*v.w;
            float dq = v.x*q4.x + v.y*q4.y + v.z*q4.z + v.w*q4.w;
            #pragma unroll
            for (int o = 16; o; o >>= 1) {
                ss += __shfl_xor_sync(0xffffffffu, ss, o);
                dq += __shfl_xor_sync(0xffffffffu, dq, o);
            }
            if (lane == 0)
                out[(size_t)r * LD_ + 1 + KQ + s] = dq / fmaxf(sqrtf(ss), 1e-12f) * INV_T;
        }
        // type 2
        {
            int g = hsh[i2[r * 16 + s]];
            float bb = beta[r * 16 + s] * 0.5f;
            float4 n1 = *(const float4*)(queue + (size_t)g * D_ + lane * 4);
            float4 v;
            v.x = bb * q4.x + (1.f - bb) * n1.x;
            v.y = bb * q4.y + (1.f - bb) * n1.y;
            v.z = bb * q4.z + (1.f - bb) * n1.z;
            v.w = bb * q4.w + (1.f - bb) * n1.w;
            float ss = v.x*v.x + v.y*v.y + v.z*v.z + v.w*v.w;
            float dq = v.x*q4.x + v.y*q4.y + v.z*q4.z + v.w*q4.w;
            #pragma unroll
            for (int o = 16; o; o >>= 1) {
                ss += __shfl_xor_sync(0xffffffffu, ss, o);
                dq += __shfl_xor_sync(0xffffffffu, dq, o);
            }
            if (lane == 0)
                out[(size_t)r * LD_ + 1 + KQ + 16 + s] = dq / fmaxf(sqrtf(ss), 1e-12f) * INV_T;
        }
    }
}

// ---------------- tail: zero labels region (if out includes it) ------------
__global__ void k_tail(float* __restrict__ out, int total) {
    for (int j = B_ * LD_ + blockIdx.x * blockDim.x + threadIdx.x; j < total;
         j += gridDim.x * blockDim.x)
        out[j] = 0.f;
}

// ---------------- launch ---------------------------------------------------
extern "C" void kernel_launch(void* const* d_in, const int* in_sizes, int n_in,
                              void* d_out, int out_size) {
    const float* q     = (const float*)d_in[0];
    const float* k     = (const float*)d_in[1];
    const float* Wq    = (const float*)d_in[2];
    const float* Wk    = (const float*)d_in[3];
    const float* queue = (const float*)d_in[4];
    const float* alpha = (const float*)d_in[5];
    const float* beta  = (const float*)d_in[6];
    const int*   i1a   = (const int*)d_in[7];
    const int*   i1b   = (const int*)d_in[8];
    const int*   i2    = (const int*)d_in[9];
    float* out = (float*)d_out;

    cudaFuncSetAttribute(k2_gemm, cudaFuncAttributeMaxDynamicSharedMemorySize, K2_SMEM);
    cudaFuncSetAttribute(k3_topk, cudaFuncAttributeMaxDynamicSharedMemorySize, K3_SMEM);

    k1_gemm<<<dim3(16, SPLITK), 256>>>(q, k, Wq, Wk);
    k1b_norm<<<8, 256>>>(out);
    k2_gemm<<<148, 256, K2_SMEM>>>(queue, out);
    k3_topk<<<256, 256, K3_SMEM>>>(out);
    k4_mix<<<256, 256>>>(queue, alpha, beta, i1a, i1b, i2, out);
    if (out_size > B_ * LD_) k_tail<<<1, 256>>>(out, out_size);
}

// round 6
// speedup vs baseline: 1.4311x; 1.4311x over previous
#include <cuda_runtime.h>
#include <cuda_bf16.h>
#include <cstdint>
#include <cstring>

#define B_    256
#define IND   2048
#define D_    128
#define KQ    65536
#define LD_   65569              /* 1 + K + S1 + S2 */
#define INV_T (1.0f/0.07f)
#define SPLITK 8

// ---------------- device scratch (no allocation allowed) -------------------
__device__ __align__(16) float g_pq[SPLITK * B_ * D_];
__device__ __align__(16) float g_pk[SPLITK * B_ * D_];
__device__ __align__(16) float g_outq[B_ * D_];    // normalized out_q [256][128]
__device__ __align__(16) float g_outqT[D_ * B_];   // transposed      [128][256]
__device__ int g_hard[B_ * 32];

// packed f32x2 FMA (PTX-only on sm_103a; doubles fp32 MAC rate)
__device__ __forceinline__ float2 ffma2(float2 a, float2 b, float2 c) {
    unsigned long long ua, ub, uc, ud;
    memcpy(&ua, &a, 8); memcpy(&ub, &b, 8); memcpy(&uc, &c, 8);
    asm("fma.rn.f32x2 %0, %1, %2, %3;" : "=l"(ud) : "l"(ua), "l"(ub), "l"(uc));
    float2 r; memcpy(&r, &ud, 8);
    return r;
}

// ---------------- k1: encoder GEMMs, split-K=8 into partial buffers --------
__global__ void k1_gemm(const float* __restrict__ q, const float* __restrict__ kk,
                        const float* __restrict__ Wq, const float* __restrict__ Wk) {
    __shared__ float qs[16][32];
    __shared__ float ks[16][32];
    const float C0 = 0.999f;
    const float C1 = 1.0f - 0.999f;
    int t = threadIdx.x;
    int c = t & 127, h = t >> 7;          // h in {0,1}: 8 rows each
    int rb = blockIdx.x * 16;
    int k0 = blockIdx.y * (IND / SPLITK); // 256-wide K slice

    float aq[8], ak[8];
    #pragma unroll
    for (int j = 0; j < 8; j++) { aq[j] = 0.f; ak[j] = 0.f; }

    for (int kc = 0; kc < IND / SPLITK; kc += 32) {
        __syncthreads();
        #pragma unroll
        for (int e = 0; e < 2; e++) {
            int id = t + e * 256;
            int r = id >> 5, i = id & 31;
            qs[r][i] = q [(size_t)(rb + r) * IND + k0 + kc + i];
            ks[r][i] = kk[(size_t)(rb + r) * IND + k0 + kc + i];
        }
        __syncthreads();
        #pragma unroll
        for (int u0 = 0; u0 < 32; u0 += 8) {
            float wq[8], wm[8];
            #pragma unroll
            for (int u = 0; u < 8; u++) {
                float a = Wq[(size_t)(k0 + kc + u0 + u) * D_ + c];
                float b = Wk[(size_t)(k0 + kc + u0 + u) * D_ + c];
                wq[u] = a;
                wm[u] = C0 * b + C1 * a;
            }
            #pragma unroll
            for (int u = 0; u < 8; u++)
                #pragma unroll
                for (int j = 0; j < 8; j++) {
                    aq[j] = fmaf(qs[h * 8 + j][u0 + u], wq[u], aq[j]);
                    ak[j] = fmaf(ks[h * 8 + j][u0 + u], wm[u], ak[j]);
                }
        }
    }
    int sk = blockIdx.y;
    #pragma unroll
    for (int j = 0; j < 8; j++) {
        int r = rb + h * 8 + j;
        g_pq[((size_t)sk * B_ + r) * D_ + c] = aq[j];
        g_pk[((size_t)sk * B_ + r) * D_ + c] = ak[j];
    }
}

// ---------------- k1b: reduce partials, normalize, pos logit ---------------
__global__ void k1b_norm(float* __restrict__ out) {
    int t = threadIdx.x, lane = t & 31, w = t >> 5;
    int rb = blockIdx.x * 32;
    for (int rr = 0; rr < 4; rr++) {
        int r = rb + rr * 8 + w;
        float4 q4 = make_float4(0.f, 0.f, 0.f, 0.f);
        float4 k4 = make_float4(0.f, 0.f, 0.f, 0.f);
        #pragma unroll
        for (int s = 0; s < SPLITK; s++) {
            float4 a = *(const float4*)&g_pq[((size_t)s * B_ + r) * D_ + lane * 4];
            float4 b = *(const float4*)&g_pk[((size_t)s * B_ + r) * D_ + lane * 4];
            q4.x += a.x; q4.y += a.y; q4.z += a.z; q4.w += a.w;
            k4.x += b.x; k4.y += b.y; k4.z += b.z; k4.w += b.w;
        }
        float s1 = q4.x*q4.x + q4.y*q4.y + q4.z*q4.z + q4.w*q4.w;
        float s2 = k4.x*k4.x + k4.y*k4.y + k4.z*k4.z + k4.w*k4.w;
        float s3 = q4.x*k4.x + q4.y*k4.y + q4.z*k4.z + q4.w*k4.w;
        #pragma unroll
        for (int o = 16; o; o >>= 1) {
            s1 += __shfl_xor_sync(0xffffffffu, s1, o);
            s2 += __shfl_xor_sync(0xffffffffu, s2, o);
            s3 += __shfl_xor_sync(0xffffffffu, s3, o);
        }
        float invq = 1.f / fmaxf(sqrtf(s1), 1e-12f);
        float invk = 1.f / fmaxf(sqrtf(s2), 1e-12f);
        float4 nq;
        nq.x = q4.x * invq; nq.y = q4.y * invq; nq.z = q4.z * invq; nq.w = q4.w * invq;
        *(float4*)&g_outq[(size_t)r * D_ + lane * 4] = nq;
        g_outqT[(lane * 4 + 0) * B_ + r] = nq.x;
        g_outqT[(lane * 4 + 1) * B_ + r] = nq.y;
        g_outqT[(lane * 4 + 2) * B_ + r] = nq.z;
        g_outqT[(lane * 4 + 3) * B_ + r] = nq.w;
        if (lane == 0) out[(size_t)r * LD_] = s3 * invq * invk * INV_T;
    }
}

// ---------------- k2: main GEMM 256 x 65536 x 128, packed f32x2 ------------
// 512 threads. warp w -> rows w*16 + (lane>>4)*8 (8 rows as 4 row-pairs),
// cols (lane&15) + o*16 (o=0..3). Stores: 16 consecutive lanes hit 16
// consecutive floats -> ~4 wavefronts per warp-STG (was 32). B prefetched.
#define AST 256
#define BST 65
#define K2_SMEM ((128*AST + 128*BST) * 4)

__global__ void __launch_bounds__(512, 1)
k2_gemm(const float* __restrict__ queue, float* __restrict__ out) {
    extern __shared__ __align__(16) float sm[];
    float* As = sm;                 // [k][m] 128 x 256
    float* Bs = sm + 128 * AST;     // [k][n] 128 x 65 (pad)
    int t = threadIdx.x, lane = t & 31, w = t >> 5;
    int rg = lane >> 4, cl = lane & 15;
    int base_m = w * 16 + rg * 8;

    // resident A load (g_outqT is [k][m]; coalesced LDG.128, conflict-free STS.128)
    #pragma unroll
    for (int e = 0; e < 16; e++) {
        int idx4 = t + e * 512;
        int kk2 = idx4 >> 6;
        int m4  = (idx4 & 63) * 4;
        *(float4*)(As + kk2 * AST + m4) = *(const float4*)(g_outqT + kk2 * B_ + m4);
    }

    int ci = blockIdx.x;
    float4 pf[4];
    if (ci < KQ / 64) {
        int nb = ci * 64;
        #pragma unroll
        for (int e = 0; e < 4; e++) {
            int idx4 = t + e * 512;
            int n = idx4 >> 5, k4 = (idx4 & 31) * 4;
            pf[e] = *(const float4*)(queue + (size_t)(nb + n) * D_ + k4);
        }
    }

    for (; ci < KQ / 64; ci += gridDim.x) {
        int nb = ci * 64;
        __syncthreads();   // As visible (1st iter) / Bs free (later iters)
        #pragma unroll
        for (int e = 0; e < 4; e++) {
            int idx4 = t + e * 512;
            int n = idx4 >> 5, k4 = (idx4 & 31) * 4;
            Bs[(k4 + 0) * BST + n] = pf[e].x;
            Bs[(k4 + 1) * BST + n] = pf[e].y;
            Bs[(k4 + 2) * BST + n] = pf[e].z;
            Bs[(k4 + 3) * BST + n] = pf[e].w;
        }
        __syncthreads();

        int ci2 = ci + gridDim.x;               // prefetch next chunk behind compute
        if (ci2 < KQ / 64) {
            int nb2 = ci2 * 64;
            #pragma unroll
            for (int e = 0; e < 4; e++) {
                int idx4 = t + e * 512;
                int n = idx4 >> 5, k4 = (idx4 & 31) * 4;
                pf[e] = *(const float4*)(queue + (size_t)(nb2 + n) * D_ + k4);
            }
        }

        float2 acc[4][4];
        #pragma unroll
        for (int p = 0; p < 4; p++)
            #pragma unroll
            for (int o = 0; o < 4; o++) { acc[p][o].x = 0.f; acc[p][o].y = 0.f; }

        #pragma unroll 4
        for (int k = 0; k < 128; k++) {
            float4 a0 = *(const float4*)(As + k * AST + base_m);
            float4 a1 = *(const float4*)(As + k * AST + base_m + 4);
            float2 rp0 = make_float2(a0.x, a0.y);
            float2 rp1 = make_float2(a0.z, a0.w);
            float2 rp2 = make_float2(a1.x, a1.y);
            float2 rp3 = make_float2(a1.z, a1.w);
            const float* br = Bs + k * BST + cl;
            #pragma unroll
            for (int o = 0; o < 4; o++) {
                float b = br[o * 16];
                float2 bb = make_float2(b, b);
                acc[0][o] = ffma2(rp0, bb, acc[0][o]);
                acc[1][o] = ffma2(rp1, bb, acc[1][o]);
                acc[2][o] = ffma2(rp2, bb, acc[2][o]);
                acc[3][o] = ffma2(rp3, bb, acc[3][o]);
            }
        }

        #pragma unroll
        for (int p = 0; p < 4; p++) {
            size_t r0 = (size_t)(base_m + p * 2) * LD_ + 1 + nb + cl;
            #pragma unroll
            for (int o = 0; o < 4; o++) {
                out[r0 + o * 16]       = acc[p][o].x * INV_T;
                out[r0 + LD_ + o * 16] = acc[p][o].y * INV_T;
            }
        }
    }
}

// ---------------- k3: exact top-32 per row -------------------------------
// hist threshold (8192 bins on monotone float key) -> candidate collect ->
// single rank-by-counting pass (keys unique: (fkey<<32)|~idx reproduces
// jax tie-break: descending value, lower index first).
#define NBIN 8192
#define CAP  1024
#define K3_SMEM (NBIN * 4 + CAP * 8)

__device__ __forceinline__ unsigned fkey(float f) {
    unsigned u = __float_as_uint(f);
    return (u >> 31) ? ~u : (u | 0x80000000u);
}

__global__ void __launch_bounds__(512)
k3_topk(const float* __restrict__ out) {
    extern __shared__ __align__(16) unsigned sm3[];
    unsigned* hist = sm3;
    unsigned long long* cand = (unsigned long long*)(sm3 + NBIN);
    __shared__ unsigned scnt[256];
    __shared__ unsigned s_tbin, s_cc;
    int t = threadIdx.x;
    int r = blockIdx.x;
    size_t base = (size_t)r * LD_ + 1;
    const float* row = out + base;
    int pre = (int)((4 - (base & 3)) & 3);      // scalars before 16B boundary
    int nv  = (KQ - pre) >> 2;
    const float4* rv = (const float4*)(row + pre);
    int rem = pre + nv * 4;

    for (int i = t; i < NBIN; i += 512) hist[i] = 0;
    if (t == 0) s_cc = 0;
    __syncthreads();

    // pass 1: histogram
    if (t < pre)        atomicAdd(&hist[fkey(row[t]) >> 19], 1u);
    if (t < KQ - rem)   atomicAdd(&hist[fkey(row[rem + t]) >> 19], 1u);
    for (int i = t; i < nv; i += 512) {
        float4 v = rv[i];
        atomicAdd(&hist[fkey(v.x) >> 19], 1u);
        atomicAdd(&hist[fkey(v.y) >> 19], 1u);
        atomicAdd(&hist[fkey(v.z) >> 19], 1u);
        atomicAdd(&hist[fkey(v.w) >> 19], 1u);
    }
    __syncthreads();

    if (t < 256) {
        unsigned loc = 0;
        #pragma unroll 4
        for (int i = 0; i < 32; i++) loc += hist[t * 32 + i];
        scnt[t] = loc;
    }
    __syncthreads();

    if (t == 0) {
        unsigned cum = 0; int seg = 255;
        for (; seg >= 0; seg--) { cum += scnt[seg]; if (cum >= 32) break; }
        unsigned cum2 = cum - scnt[seg];
        int tb = seg * 32;
        for (int i = 31; i >= 0; i--) {
            cum2 += hist[seg * 32 + i];
            if (cum2 >= 32) { tb = seg * 32 + i; break; }
        }
        s_tbin = (unsigned)tb;
    }
    __syncthreads();

    // pass 2: collect candidates (>= threshold bin)
    unsigned tb = s_tbin;
    if (t < pre) {
        unsigned fk = fkey(row[t]);
        if ((fk >> 19) >= tb) {
            unsigned pos = atomicAdd(&s_cc, 1u);
            if (pos < CAP) cand[pos] = ((unsigned long long)fk << 32) | (unsigned)(~(unsigned)t);
        }
    }
    if (t < KQ - rem) {
        unsigned fk = fkey(row[rem + t]);
        if ((fk >> 19) >= tb) {
            unsigned pos = atomicAdd(&s_cc, 1u);
            if (pos < CAP) cand[pos] = ((unsigned long long)fk << 32) | (unsigned)(~(unsigned)(rem + t));
        }
    }
    for (int i = t; i < nv; i += 512) {
        float4 v = rv[i];
        float vals[4] = {v.x, v.y, v.z, v.w};
        #pragma unroll
        for (int c = 0; c < 4; c++) {
            unsigned fk = fkey(vals[c]);
            if ((fk >> 19) >= tb) {
                unsigned pos = atomicAdd(&s_cc, 1u);
                if (pos < CAP)
                    cand[pos] = ((unsigned long long)fk << 32) | (unsigned)(~(unsigned)(pre + i * 4 + c));
            }
        }
    }
    __syncthreads();
    int n = (int)min(s_cc, (unsigned)CAP);

    // rank-by-counting: one pass, exact, order-independent
    for (int i = t; i < n; i += 512) {
        unsigned long long key = cand[i];
        int rank = 0;
        for (int j = 0; j < n; j++) rank += (cand[j] > key) ? 1 : 0;
        if (rank < 32) g_hard[r * 32 + rank] = (int)(~(unsigned)(key & 0xFFFFFFFFull));
    }
}

// ---------------- k4: mixed hard-negative logits ---------------------------
__global__ void k4_mix(const float* __restrict__ queue, const float* __restrict__ alpha,
                       const float* __restrict__ beta, const int* __restrict__ i1a,
                       const int* __restrict__ i1b, const int* __restrict__ i2,
                       float* __restrict__ out) {
    __shared__ float qsh[D_];
    __shared__ int hsh[32];
    int t = threadIdx.x, lane = t & 31, w = t >> 5;
    int r = blockIdx.x;
    if (t < D_) qsh[t] = g_outq[(size_t)r * D_ + t];
    if (t < 32) hsh[t] = g_hard[r * 32 + t];
    __syncthreads();
    float4 q4 = *(float4*)&qsh[lane * 4];

    #pragma unroll
    for (int e = 0; e < 2; e++) {
        int s = w * 2 + e;
        // type 1
        {
            int g1 = hsh[i1a[r * 16 + s]];
            int g2 = hsh[i1b[r * 16 + s]];
            float a = alpha[r * 16 + s];
            float4 n1 = *(const float4*)(queue + (size_t)g1 * D_ + lane * 4);
            float4 n2 = *(const float4*)(queue + (size_t)g2 * D_ + lane * 4);
            float4 v;
            v.x = a * n1.x + (1.f - a) * n2.x;
            v.y = a * n1.y + (1.f - a) * n2.y;
            v.z = a * n1.z + (1.f - a) * n2.z;
            v.w = a * n1.w + (1.f - a) * n2.w;
            float ss = v.x*v.x + v.y*v.y + v.z*v.z + v.w*v.w;
            float dq = v.x*q4.x + v.y*q4.y + v.z*q4.z + v.w*q4.w;
            #pragma unroll
            for (int o = 16; o; o >>= 1) {
                ss += __shfl_xor_sync(0xffffffffu, ss, o);
                dq += __shfl_xor_sync(0xffffffffu, dq, o);
            }
            if (lane == 0)
                out[(size_t)r * LD_ + 1 + KQ + s] = dq / fmaxf(sqrtf(ss), 1e-12f) * INV_T;
        }
        // type 2
        {
            int g = hsh[i2[r * 16 + s]];
            float bb = beta[r * 16 + s] * 0.5f;
            float4 n1 = *(const float4*)(queue + (size_t)g * D_ + lane * 4);
            float4 v;
            v.x = bb * q4.x + (1.f - bb) * n1.x;
            v.y = bb * q4.y + (1.f - bb) * n1.y;
            v.z = bb * q4.z + (1.f - bb) * n1.z;
            v.w = bb * q4.w + (1.f - bb) * n1.w;
            float ss = v.x*v.x + v.y*v.y + v.z*v.z + v.w*v.w;
            float dq = v.x*q4.x + v.y*q4.y + v.z*q4.z + v.w*q4.w;
            #pragma unroll
            for (int o = 16; o; o >>= 1) {
                ss += __shfl_xor_sync(0xffffffffu, ss, o);
                dq += __shfl_xor_sync(0xffffffffu, dq, o);
            }
            if (lane == 0)
                out[(size_t)r * LD_ + 1 + KQ + 16 + s] = dq / fmaxf(sqrtf(ss), 1e-12f) * INV_T;
        }
    }
}

// ---------------- tail: zero labels region (if out includes it) ------------
__global__ void k_tail(float* __restrict__ out, int total) {
    for (int j = B_ * LD_ + blockIdx.x * blockDim.x + threadIdx.x; j < total;
         j += gridDim.x * blockDim.x)
        out[j] = 0.f;
}

// ---------------- launch ---------------------------------------------------
extern "C" void kernel_launch(void* const* d_in, const int* in_sizes, int n_in,
                              void* d_out, int out_size) {
    const float* q     = (const float*)d_in[0];
    const float* k     = (const float*)d_in[1];
    const float* Wq    = (const float*)d_in[2];
    const float* Wk    = (const float*)d_in[3];
    const float* queue = (const float*)d_in[4];
    const float* alpha = (const float*)d_in[5];
    const float* beta  = (const float*)d_in[6];
    const int*   i1a   = (const int*)d_in[7];
    const int*   i1b   = (const int*)d_in[8];
    const int*   i2    = (const int*)d_in[9];
    float* out = (float*)d_out;

    cudaFuncSetAttribute(k2_gemm, cudaFuncAttributeMaxDynamicSharedMemorySize, K2_SMEM);
    cudaFuncSetAttribute(k3_topk, cudaFuncAttributeMaxDynamicSharedMemorySize, K3_SMEM);

    k1_gemm<<<dim3(16, SPLITK), 256>>>(q, k, Wq, Wk);
    k1b_norm<<<8, 256>>>(out);
    k2_gemm<<<148, 512, K2_SMEM>>>(queue, out);
    k3_topk<<<256, 512, K3_SMEM>>>(out);
    k4_mix<<<256, 256>>>(queue, alpha, beta, i1a, i1b, i2, out);
    if (out_size > B_ * LD_) k_tail<<<1, 256>>>(out, out_size);
}

// round 7
// speedup vs baseline: 1.4794x; 1.0338x over previous
#include <cuda_runtime.h>
#include <cuda_bf16.h>
#include <cstdint>
#include <cstring>

#define B_    256
#define IND   2048
#define D_    128
#define KQ    65536
#define LD_   65569              /* 1 + K + S1 + S2 */
#define INV_T (1.0f/0.07f)
#define SPLITK 8
#define NCHUNK 1024              /* KQ / 64 */
#define CAP    2048

// ---------------- device scratch (no allocation allowed) -------------------
__device__ __align__(16) float g_pq[SPLITK * B_ * D_];
__device__ __align__(16) float g_pk[SPLITK * B_ * D_];
__device__ __align__(16) float g_outq[B_ * D_];    // normalized out_q [256][128]
__device__ __align__(16) float g_outqT[D_ * B_];   // transposed      [128][256]
__device__ __align__(16) float g_cmax[B_ * NCHUNK];// per-row per-64chunk max
__device__ __align__(16) unsigned long long g_cand[B_ * CAP];
__device__ unsigned g_ccnt[B_];
__device__ int g_hard[B_ * 32];

// packed f32x2 FMA (PTX-only on sm_103a; doubles fp32 MAC rate)
__device__ __forceinline__ float2 ffma2(float2 a, float2 b, float2 c) {
    unsigned long long ua, ub, uc, ud;
    memcpy(&ua, &a, 8); memcpy(&ub, &b, 8); memcpy(&uc, &c, 8);
    asm("fma.rn.f32x2 %0, %1, %2, %3;" : "=l"(ud) : "l"(ua), "l"(ub), "l"(uc));
    float2 r; memcpy(&r, &ud, 8);
    return r;
}

__device__ __forceinline__ unsigned fkey(float f) {
    unsigned u = __float_as_uint(f);
    return (u >> 31) ? ~u : (u | 0x80000000u);
}

// ---------------- k1: encoder GEMMs, split-K=8 into partial buffers --------
__global__ void k1_gemm(const float* __restrict__ q, const float* __restrict__ kk,
                        const float* __restrict__ Wq, const float* __restrict__ Wk) {
    __shared__ float qs[16][32];
    __shared__ float ks[16][32];
    const float C0 = 0.999f;
    const float C1 = 1.0f - 0.999f;
    int t = threadIdx.x;
    int c = t & 127, h = t >> 7;
    int rb = blockIdx.x * 16;
    int k0 = blockIdx.y * (IND / SPLITK);

    float aq[8], ak[8];
    #pragma unroll
    for (int j = 0; j < 8; j++) { aq[j] = 0.f; ak[j] = 0.f; }

    for (int kc = 0; kc < IND / SPLITK; kc += 32) {
        __syncthreads();
        #pragma unroll
        for (int e = 0; e < 2; e++) {
            int id = t + e * 256;
            int r = id >> 5, i = id & 31;
            qs[r][i] = q [(size_t)(rb + r) * IND + k0 + kc + i];
            ks[r][i] = kk[(size_t)(rb + r) * IND + k0 + kc + i];
        }
        __syncthreads();
        #pragma unroll
        for (int u0 = 0; u0 < 32; u0 += 8) {
            float wq[8], wm[8];
            #pragma unroll
            for (int u = 0; u < 8; u++) {
                float a = Wq[(size_t)(k0 + kc + u0 + u) * D_ + c];
                float b = Wk[(size_t)(k0 + kc + u0 + u) * D_ + c];
                wq[u] = a;
                wm[u] = C0 * b + C1 * a;
            }
            #pragma unroll
            for (int u = 0; u < 8; u++)
                #pragma unroll
                for (int j = 0; j < 8; j++) {
                    aq[j] = fmaf(qs[h * 8 + j][u0 + u], wq[u], aq[j]);
                    ak[j] = fmaf(ks[h * 8 + j][u0 + u], wm[u], ak[j]);
                }
        }
    }
    int sk = blockIdx.y;
    #pragma unroll
    for (int j = 0; j < 8; j++) {
        int r = rb + h * 8 + j;
        g_pq[((size_t)sk * B_ + r) * D_ + c] = aq[j];
        g_pk[((size_t)sk * B_ + r) * D_ + c] = ak[j];
    }
}

// ---------------- k1b: reduce partials, normalize, pos logit ---------------
__global__ void k1b_norm(float* __restrict__ out) {
    int t = threadIdx.x, lane = t & 31, w = t >> 5;
    int rb = blockIdx.x * 32;
    if (blockIdx.x == 0 && t < B_) g_ccnt[t] = 0;   // reset candidate counters
    for (int rr = 0; rr < 4; rr++) {
        int r = rb + rr * 8 + w;
        float4 q4 = make_float4(0.f, 0.f, 0.f, 0.f);
        float4 k4 = make_float4(0.f, 0.f, 0.f, 0.f);
        #pragma unroll
        for (int s = 0; s < SPLITK; s++) {
            float4 a = *(const float4*)&g_pq[((size_t)s * B_ + r) * D_ + lane * 4];
            float4 b = *(const float4*)&g_pk[((size_t)s * B_ + r) * D_ + lane * 4];
            q4.x += a.x; q4.y += a.y; q4.z += a.z; q4.w += a.w;
            k4.x += b.x; k4.y += b.y; k4.z += b.z; k4.w += b.w;
        }
        float s1 = q4.x*q4.x + q4.y*q4.y + q4.z*q4.z + q4.w*q4.w;
        float s2 = k4.x*k4.x + k4.y*k4.y + k4.z*k4.z + k4.w*k4.w;
        float s3 = q4.x*k4.x + q4.y*k4.y + q4.z*k4.z + q4.w*k4.w;
        #pragma unroll
        for (int o = 16; o; o >>= 1) {
            s1 += __shfl_xor_sync(0xffffffffu, s1, o);
            s2 += __shfl_xor_sync(0xffffffffu, s2, o);
            s3 += __shfl_xor_sync(0xffffffffu, s3, o);
        }
        float invq = 1.f / fmaxf(sqrtf(s1), 1e-12f);
        float invk = 1.f / fmaxf(sqrtf(s2), 1e-12f);
        float4 nq;
        nq.x = q4.x * invq; nq.y = q4.y * invq; nq.z = q4.z * invq; nq.w = q4.w * invq;
        *(float4*)&g_outq[(size_t)r * D_ + lane * 4] = nq;
        g_outqT[(lane * 4 + 0) * B_ + r] = nq.x;
        g_outqT[(lane * 4 + 1) * B_ + r] = nq.y;
        g_outqT[(lane * 4 + 2) * B_ + r] = nq.z;
        g_outqT[(lane * 4 + 3) * B_ + r] = nq.w;
        if (lane == 0) out[(size_t)r * LD_] = s3 * invq * invk * INV_T;
    }
}

// ---------------- k2: main GEMM 256 x 65536 x 128 --------------------------
// 256 threads, thread tile 16 rows x 4 cols.
// A: [k][256] smem (broadcast reads). B: [n][k] smem stride 132 — STS.128
// conflict-free, reads 1 LDS.128 per 4 k per col. Epilogue also emits
// per-(row,chunk) max for k3's threshold (g_cmax).
#define AST  256
#define BST2 132
#define K2_SMEM ((128*AST + 64*BST2) * 4)

__global__ void __launch_bounds__(256, 1)
k2_gemm(const float* __restrict__ queue, float* __restrict__ out) {
    extern __shared__ __align__(16) float sm[];
    float* As = sm;                 // [k][m] 128 x 256
    float* Bs = sm + 128 * AST;     // [n][k] 64 x 132
    int t = threadIdx.x, lane = t & 31, w = t >> 5;
    int rg = lane >> 4, cl = lane & 15;
    int base_m = w * 32 + rg * 16;          // 16 rows per thread

    // resident A load (g_outqT is [k][m]; coalesced LDG.128, conflict-free STS.128)
    #pragma unroll
    for (int e = 0; e < 32; e++) {
        int idx4 = t + e * 256;
        int kk2 = idx4 >> 6;
        int m4  = (idx4 & 63) * 4;
        *(float4*)(As + kk2 * AST + m4) = *(const float4*)(g_outqT + kk2 * B_ + m4);
    }

    int ci = blockIdx.x;
    float4 pf[8];
    if (ci < NCHUNK) {
        int nb = ci * 64;
        #pragma unroll
        for (int e = 0; e < 8; e++) {
            int idx4 = t + e * 256;
            int n = idx4 >> 5, k4 = (idx4 & 31) * 4;
            pf[e] = *(const float4*)(queue + (size_t)(nb + n) * D_ + k4);
        }
    }

    for (; ci < NCHUNK; ci += gridDim.x) {
        int nb = ci * 64;
        __syncthreads();   // As visible (1st iter) / Bs free (later iters)
        #pragma unroll
        for (int e = 0; e < 8; e++) {
            int idx4 = t + e * 256;
            int n = idx4 >> 5, k4 = (idx4 & 31) * 4;
            *(float4*)(Bs + n * BST2 + k4) = pf[e];   // STS.128, conflict-free
        }
        __syncthreads();

        int ci2 = ci + gridDim.x;               // prefetch next chunk behind compute
        if (ci2 < NCHUNK) {
            int nb2 = ci2 * 64;
            #pragma unroll
            for (int e = 0; e < 8; e++) {
                int idx4 = t + e * 256;
                int n = idx4 >> 5, k4 = (idx4 & 31) * 4;
                pf[e] = *(const float4*)(queue + (size_t)(nb2 + n) * D_ + k4);
            }
        }

        float2 acc[8][4];                       // 8 row-pairs x 4 cols
        #pragma unroll
        for (int j = 0; j < 8; j++)
            #pragma unroll
            for (int o = 0; o < 4; o++) { acc[j][o].x = 0.f; acc[j][o].y = 0.f; }

        for (int k0 = 0; k0 < 128; k0 += 4) {
            float bcol[4][4];
            #pragma unroll
            for (int o = 0; o < 4; o++) {
                float4 bq = *(const float4*)(Bs + (cl + o * 16) * BST2 + k0);
                bcol[o][0] = bq.x; bcol[o][1] = bq.y; bcol[o][2] = bq.z; bcol[o][3] = bq.w;
            }
            #pragma unroll
            for (int kk2 = 0; kk2 < 4; kk2++) {
                const float* ar = As + (k0 + kk2) * AST + base_m;
                float4 a0 = *(const float4*)(ar);
                float4 a1 = *(const float4*)(ar + 4);
                float4 a2 = *(const float4*)(ar + 8);
                float4 a3 = *(const float4*)(ar + 12);
                float2 pr[8];
                pr[0] = make_float2(a0.x, a0.y); pr[1] = make_float2(a0.z, a0.w);
                pr[2] = make_float2(a1.x, a1.y); pr[3] = make_float2(a1.z, a1.w);
                pr[4] = make_float2(a2.x, a2.y); pr[5] = make_float2(a2.z, a2.w);
                pr[6] = make_float2(a3.x, a3.y); pr[7] = make_float2(a3.z, a3.w);
                #pragma unroll
                for (int o = 0; o < 4; o++) {
                    float2 bb = make_float2(bcol[o][kk2], bcol[o][kk2]);
                    #pragma unroll
                    for (int j = 0; j < 8; j++)
                        acc[j][o] = ffma2(pr[j], bb, acc[j][o]);
                }
            }
        }

        // stores (cols cl + o*16: 16 consecutive lanes -> consecutive floats)
        #pragma unroll
        for (int j = 0; j < 8; j++) {
            size_t o0 = (size_t)(base_m + 2 * j) * LD_ + 1 + nb + cl;
            #pragma unroll
            for (int o = 0; o < 4; o++) {
                out[o0 + o * 16]       = acc[j][o].x * INV_T;
                out[o0 + LD_ + o * 16] = acc[j][o].y * INV_T;
            }
        }

        // per-row chunk max -> g_cmax (reduce over cl lanes)
        float rmax[16];
        #pragma unroll
        for (int j = 0; j < 8; j++) {
            rmax[2*j]   = fmaxf(fmaxf(acc[j][0].x, acc[j][1].x), fmaxf(acc[j][2].x, acc[j][3].x));
            rmax[2*j+1] = fmaxf(fmaxf(acc[j][0].y, acc[j][1].y), fmaxf(acc[j][2].y, acc[j][3].y));
        }
        #pragma unroll
        for (int sh = 1; sh < 16; sh <<= 1)
            #pragma unroll
            for (int i = 0; i < 16; i++)
                rmax[i] = fmaxf(rmax[i], __shfl_xor_sync(0xffffffffu, rmax[i], sh));
        if (cl == 0) {
            #pragma unroll
            for (int i = 0; i < 16; i++)
                g_cmax[(size_t)(base_m + i) * NCHUNK + ci] = rmax[i] * INV_T;
        }
    }
}

// ---------------- k3a: threshold from chunk maxima, collect candidates -----
// 4 blocks per row (quarter rows). Threshold: find bin tb such that >= 32
// chunk-maxima land in bins >= tb  =>  >= 32 elements >= bin_floor(tb).
#define NBIN 8192
#define K3A_SMEM (NBIN * 4)

__global__ void __launch_bounds__(512)
k3a_collect(const float* __restrict__ out) {
    extern __shared__ __align__(16) unsigned sm3[];
    unsigned* hist = sm3;
    __shared__ unsigned scnt[256];
    __shared__ unsigned s_tbin;
    int t = threadIdx.x;
    int r = blockIdx.x >> 2, qt = blockIdx.x & 3;

    for (int i = t; i < NBIN; i += 512) hist[i] = 0;
    __syncthreads();

    for (int i = t; i < NCHUNK; i += 512)
        atomicAdd(&hist[fkey(g_cmax[(size_t)r * NCHUNK + i]) >> 19], 1u);
    __syncthreads();

    if (t < 256) {
        unsigned loc = 0;
        #pragma unroll 4
        for (int i = 0; i < 32; i++) loc += hist[t * 32 + i];
        scnt[t] = loc;
    }
    __syncthreads();

    if (t == 0) {
        unsigned cum = 0; int seg = 255;
        for (; seg >= 0; seg--) { cum += scnt[seg]; if (cum >= 32) break; }
        unsigned cum2 = cum - scnt[seg];
        int tb = seg * 32;
        for (int i = 31; i >= 0; i--) {
            cum2 += hist[seg * 32 + i];
            if (cum2 >= 32) { tb = seg * 32 + i; break; }
        }
        s_tbin = (unsigned)tb;
    }
    __syncthreads();

    unsigned tb = s_tbin;
    const int QLEN = KQ / 4;
    size_t base = (size_t)r * LD_ + 1 + (size_t)qt * QLEN;
    const float* seg = out + base;
    int j0 = qt * QLEN;
    int pre = (int)((4 - (base & 3)) & 3);
    int nv  = (QLEN - pre) >> 2;
    int rem = pre + nv * 4;
    const float4* sv = (const float4*)(seg + pre);

    if (t < pre) {
        unsigned fk = fkey(seg[t]);
        if ((fk >> 19) >= tb) {
            unsigned pos = atomicAdd(&g_ccnt[r], 1u);
            if (pos < CAP)
                g_cand[(size_t)r * CAP + pos] =
                    ((unsigned long long)fk << 32) | (unsigned)(~(unsigned)(j0 + t));
        }
    }
    if (t < QLEN - rem) {
        unsigned fk = fkey(seg[rem + t]);
        if ((fk >> 19) >= tb) {
            unsigned pos = atomicAdd(&g_ccnt[r], 1u);
            if (pos < CAP)
                g_cand[(size_t)r * CAP + pos] =
                    ((unsigned long long)fk << 32) | (unsigned)(~(unsigned)(j0 + rem + t));
        }
    }
    for (int i = t; i < nv; i += 512) {
        float4 v = sv[i];
        float vals[4] = {v.x, v.y, v.z, v.w};
        #pragma unroll
        for (int c = 0; c < 4; c++) {
            unsigned fk = fkey(vals[c]);
            if ((fk >> 19) >= tb) {
                unsigned pos = atomicAdd(&g_ccnt[r], 1u);
                if (pos < CAP)
                    g_cand[(size_t)r * CAP + pos] =
                        ((unsigned long long)fk << 32) | (unsigned)(~(unsigned)(j0 + pre + i * 4 + c));
            }
        }
    }
}

// ---------------- k3b: exact rank-by-count over candidates -----------------
__global__ void __launch_bounds__(256)
k3b_rank() {
    __shared__ unsigned long long cand[CAP];
    int t = threadIdx.x;
    int r = blockIdx.x;
    int n = (int)min(g_ccnt[r], (unsigned)CAP);
    for (int i = t; i < n; i += 256) cand[i] = g_cand[(size_t)r * CAP + i];
    __syncthreads();
    for (int i = t; i < n; i += 256) {
        unsigned long long key = cand[i];
        int rank = 0;
        for (int j = 0; j < n; j++) rank += (cand[j] > key) ? 1 : 0;
        if (rank < 32) g_hard[r * 32 + rank] = (int)(~(unsigned)(key & 0xFFFFFFFFull));
    }
}

// ---------------- k4: mixed hard-negative logits ---------------------------
__global__ void k4_mix(const float* __restrict__ queue, const float* __restrict__ alpha,
                       const float* __restrict__ beta, const int* __restrict__ i1a,
                       const int* __restrict__ i1b, const int* __restrict__ i2,
                       float* __restrict__ out) {
    __shared__ float qsh[D_];
    __shared__ int hsh[32];
    int t = threadIdx.x, lane = t & 31, w = t >> 5;
    int r = blockIdx.x;
    if (t < D_) qsh[t] = g_outq[(size_t)r * D_ + t];
    if (t < 32) hsh[t] = g_hard[r * 32 + t];
    __syncthreads();
    float4 q4 = *(float4*)&qsh[lane * 4];

    #pragma unroll
    for (int e = 0; e < 2; e++) {
        int s = w * 2 + e;
        {
            int g1 = hsh[i1a[r * 16 + s]];
            int g2 = hsh[i1b[r * 16 + s]];
            float a = alpha[r * 16 + s];
            float4 n1 = *(const float4*)(queue + (size_t)g1 * D_ + lane * 4);
            float4 n2 = *(const float4*)(queue + (size_t)g2 * D_ + lane * 4);
            float4 v;
            v.x = a * n1.x + (1.f - a) * n2.x;
            v.y = a * n1.y + (1.f - a) * n2.y;
            v.z = a * n1.z + (1.f - a) * n2.z;
            v.w = a * n1.w + (1.f - a) * n2.w;
            float ss = v.x*v.x + v.y*v.y + v.z*v.z + v.w*v.w;
            float dq = v.x*q4.x + v.y*q4.y + v.z*q4.z + v.w*q4.w;
            #pragma unroll
            for (int o = 16; o; o >>= 1) {
                ss += __shfl_xor_sync(0xffffffffu, ss, o);
                dq += __shfl_xor_sync(0xffffffffu, dq, o);
            }
            if (lane == 0)
                out[(size_t)r * LD_ + 1 + KQ + s] = dq / fmaxf(sqrtf(ss), 1e-12f) * INV_T;
        }
        {
            int g = hsh[i2[r * 16 + s]];
            float bb = beta[r * 16 + s] * 0.5f;
            float4 n1 = *(const float4*)(queue + (size_t)g * D_ + lane * 4);
            float4 v;
            v.x = bb * q4.x + (1.f - bb) * n1.x;
            v.y = bb * q4.y + (1.f - bb) * n1.y;
            v.z = bb * q4.z + (1.f - bb) * n1.z;
            v.w = bb * q4.w + (1.f - bb) * n1.w;
            float ss = v.x*v.x + v.y*v.y + v.z*v.z + v.w*v.w;
            float dq = v.x*q4.x + v.y*q4.y + v.z*q4.z + v.w*q4.w;
            #pragma unroll
            for (int o = 16; o; o >>= 1) {
                ss += __shfl_xor_sync(0xffffffffu, ss, o);
                dq += __shfl_xor_sync(0xffffffffu, dq, o);
            }
            if (lane == 0)
                out[(size_t)r * LD_ + 1 + KQ + 16 + s] = dq / fmaxf(sqrtf(ss), 1e-12f) * INV_T;
        }
    }
}

// ---------------- tail: zero labels region (if out includes it) ------------
__global__ void k_tail(float* __restrict__ out, int total) {
    for (int j = B_ * LD_ + blockIdx.x * blockDim.x + threadIdx.x; j < total;
         j += gridDim.x * blockDim.x)
        out[j] = 0.f;
}

// ---------------- launch ---------------------------------------------------
extern "C" void kernel_launch(void* const* d_in, const int* in_sizes, int n_in,
                              void* d_out, int out_size) {
    const float* q     = (const float*)d_in[0];
    const float* k     = (const float*)d_in[1];
    const float* Wq    = (const float*)d_in[2];
    const float* Wk    = (const float*)d_in[3];
    const float* queue = (const float*)d_in[4];
    const float* alpha = (const float*)d_in[5];
    const float* beta  = (const float*)d_in[6];
    const int*   i1a   = (const int*)d_in[7];
    const int*   i1b   = (const int*)d_in[8];
    const int*   i2    = (const int*)d_in[9];
    float* out = (float*)d_out;

    cudaFuncSetAttribute(k2_gemm, cudaFuncAttributeMaxDynamicSharedMemorySize, K2_SMEM);
    cudaFuncSetAttribute(k3a_collect, cudaFuncAttributeMaxDynamicSharedMemorySize, K3A_SMEM);

    k1_gemm<<<dim3(16, SPLITK), 256>>>(q, k, Wq, Wk);
    k1b_norm<<<8, 256>>>(out);
    k2_gemm<<<148, 256, K2_SMEM>>>(queue, out);
    k3a_collect<<<1024, 512, K3A_SMEM>>>(out);
    k3b_rank<<<256, 256>>>();
    k4_mix<<<256, 256>>>(queue, alpha, beta, i1a, i1b, i2, out);
    if (out_size > B_ * LD_) k_tail<<<1, 256>>>(out, out_size);
}

// round 9
// speedup vs baseline: 1.9347x; 1.3078x over previous
#include <cuda_runtime.h>
#include <cuda_bf16.h>
#include <cstdint>
#include <cstring>

#define B_    256
#define IND   2048
#define D_    128
#define KQ    65536
#define LD_   65569              /* 1 + K + S1 + S2 */
#define INV_T (1.0f/0.07f)
#define SPLITK 8
#define NCHUNK 1024              /* KQ / 64 */

// ---------------- device scratch (no allocation allowed) -------------------
__device__ __align__(16) float g_pq[SPLITK * B_ * D_];
__device__ __align__(16) float g_pk[SPLITK * B_ * D_];
__device__ __align__(16) float g_outq[B_ * D_];          // normalized out_q
__device__ __align__(16) unsigned short g_ah[B_ * D_];   // bf16 hi of out_q
__device__ __align__(16) unsigned short g_al[B_ * D_];   // bf16 lo of out_q
__device__ __align__(16) float g_cmax[B_ * NCHUNK];      // per-row 64-chunk max
__device__ int g_hard[B_ * 32];

__device__ __forceinline__ unsigned fkey(float f) {
    unsigned u = __float_as_uint(f);
    return (u >> 31) ? ~u : (u | 0x80000000u);
}

__device__ __forceinline__ uint32_t smem_u32(const void* p) {
    uint32_t a;
    asm("{ .reg .u64 t; cvta.to.shared.u64 t, %1; cvt.u32.u64 %0, t; }" : "=r"(a) : "l"(p));
    return a;
}
__device__ __forceinline__ void ldsm4(uint32_t* r, uint32_t a) {
    asm volatile("ldmatrix.sync.aligned.m8n8.x4.shared.b16 {%0,%1,%2,%3}, [%4];"
                 : "=r"(r[0]), "=r"(r[1]), "=r"(r[2]), "=r"(r[3]) : "r"(a));
}
__device__ __forceinline__ void ldsm2(uint32_t* r, uint32_t a) {
    asm volatile("ldmatrix.sync.aligned.m8n8.x2.shared.b16 {%0,%1}, [%2];"
                 : "=r"(r[0]), "=r"(r[1]) : "r"(a));
}
__device__ __forceinline__ void mma16816(float* c, const uint32_t* a, const uint32_t* b) {
    asm volatile(
        "mma.sync.aligned.m16n8k16.row.col.f32.bf16.bf16.f32 "
        "{%0,%1,%2,%3}, {%4,%5,%6,%7}, {%8,%9}, {%0,%1,%2,%3};"
        : "+f"(c[0]), "+f"(c[1]), "+f"(c[2]), "+f"(c[3])
        : "r"(a[0]), "r"(a[1]), "r"(a[2]), "r"(a[3]), "r"(b[0]), "r"(b[1]));
}

// ---------------- k1: encoder GEMMs, split-K=8 -----------------------------
__global__ void k1_gemm(const float* __restrict__ q, const float* __restrict__ kk,
                        const float* __restrict__ Wq, const float* __restrict__ Wk) {
    __shared__ float qs[16][32];
    __shared__ float ks[16][32];
    const float C0 = 0.999f, C1 = 1.0f - 0.999f;
    int t = threadIdx.x;
    int c = t & 127, h = t >> 7;
    int rb = blockIdx.x * 16;
    int k0 = blockIdx.y * (IND / SPLITK);

    float aq[8], ak[8];
    #pragma unroll
    for (int j = 0; j < 8; j++) { aq[j] = 0.f; ak[j] = 0.f; }

    for (int kc = 0; kc < IND / SPLITK; kc += 32) {
        __syncthreads();
        #pragma unroll
        for (int e = 0; e < 2; e++) {
            int id = t + e * 256;
            int r = id >> 5, i = id & 31;
            qs[r][i] = q [(size_t)(rb + r) * IND + k0 + kc + i];
            ks[r][i] = kk[(size_t)(rb + r) * IND + k0 + kc + i];
        }
        __syncthreads();
        #pragma unroll
        for (int u0 = 0; u0 < 32; u0 += 8) {
            float wq[8], wm[8];
            #pragma unroll
            for (int u = 0; u < 8; u++) {
                float a = Wq[(size_t)(k0 + kc + u0 + u) * D_ + c];
                float b = Wk[(size_t)(k0 + kc + u0 + u) * D_ + c];
                wq[u] = a;
                wm[u] = C0 * b + C1 * a;
            }
            #pragma unroll
            for (int u = 0; u < 8; u++)
                #pragma unroll
                for (int j = 0; j < 8; j++) {
                    aq[j] = fmaf(qs[h * 8 + j][u0 + u], wq[u], aq[j]);
                    ak[j] = fmaf(ks[h * 8 + j][u0 + u], wm[u], ak[j]);
                }
        }
    }
    int sk = blockIdx.y;
    #pragma unroll
    for (int j = 0; j < 8; j++) {
        int r = rb + h * 8 + j;
        g_pq[((size_t)sk * B_ + r) * D_ + c] = aq[j];
        g_pk[((size_t)sk * B_ + r) * D_ + c] = ak[j];
    }
}

// ---------------- k1b: reduce, normalize, pos logit, bf16 hi/lo split ------
__global__ void k1b_norm(float* __restrict__ out) {
    int t = threadIdx.x, lane = t & 31, w = t >> 5;
    int rb = blockIdx.x * 32;
    for (int rr = 0; rr < 4; rr++) {
        int r = rb + rr * 8 + w;
        float4 q4 = make_float4(0.f, 0.f, 0.f, 0.f);
        float4 k4 = make_float4(0.f, 0.f, 0.f, 0.f);
        #pragma unroll
        for (int s = 0; s < SPLITK; s++) {
            float4 a = *(const float4*)&g_pq[((size_t)s * B_ + r) * D_ + lane * 4];
            float4 b = *(const float4*)&g_pk[((size_t)s * B_ + r) * D_ + lane * 4];
            q4.x += a.x; q4.y += a.y; q4.z += a.z; q4.w += a.w;
            k4.x += b.x; k4.y += b.y; k4.z += b.z; k4.w += b.w;
        }
        float s1 = q4.x*q4.x + q4.y*q4.y + q4.z*q4.z + q4.w*q4.w;
        float s2 = k4.x*k4.x + k4.y*k4.y + k4.z*k4.z + k4.w*k4.w;
        float s3 = q4.x*k4.x + q4.y*k4.y + q4.z*k4.z + q4.w*k4.w;
        #pragma unroll
        for (int o = 16; o; o >>= 1) {
            s1 += __shfl_xor_sync(0xffffffffu, s1, o);
            s2 += __shfl_xor_sync(0xffffffffu, s2, o);
            s3 += __shfl_xor_sync(0xffffffffu, s3, o);
        }
        float invq = 1.f / fmaxf(sqrtf(s1), 1e-12f);
        float invk = 1.f / fmaxf(sqrtf(s2), 1e-12f);
        float vs[4] = {q4.x * invq, q4.y * invq, q4.z * invq, q4.w * invq};
        *(float4*)&g_outq[(size_t)r * D_ + lane * 4] = make_float4(vs[0], vs[1], vs[2], vs[3]);
        unsigned hs[4], ls[4];
        #pragma unroll
        for (int j = 0; j < 4; j++) {
            __nv_bfloat16 hb = __float2bfloat16_rn(vs[j]);
            float lo = vs[j] - __bfloat162float(hb);
            hs[j] = (unsigned)__bfloat16_as_ushort(hb);
            ls[j] = (unsigned)__bfloat16_as_ushort(__float2bfloat16_rn(lo));
        }
        ((uint2*)g_ah)[r * 32 + lane] = make_uint2(hs[0] | (hs[1] << 16), hs[2] | (hs[3] << 16));
        ((uint2*)g_al)[r * 32 + lane] = make_uint2(ls[0] | (ls[1] << 16), ls[2] | (ls[3] << 16));
        if (lane == 0) out[(size_t)r * LD_] = s3 * invq * invk * INV_T;
    }
}

// ---------------- k2m: HMMA bf16 3-term GEMM 256x65536x128 -----------------
// grid (1024 N-chunks of 64, 2 M-tiles of 128). Block 256 thr = 8 warps,
// warp grid 2(M)x4(N), warp tile 64x16, mma.sync.m16n8k16.
// smem tiles XOR-swizzled (16B chunk ^ (row&7)) -> conflict-free ldmatrix.
// B loaded from queue fp32, split to bf16 hi/lo in-flight.
#define AH_O 0
#define AL_O 32768
#define BH_O 65536
#define BL_O (65536 + 16384)
#define K2M_SMEM (65536 + 32768)      /* 96 KB */
#define STG_W 66

__global__ void __launch_bounds__(256, 2)
k2m_gemm(const float* __restrict__ queue, float* __restrict__ out) {
    extern __shared__ __align__(16) char smc[];
    int t = threadIdx.x, lane = t & 31, w = t >> 5;
    int wm = w & 1, wn = w >> 1;
    int ci = blockIdx.x, mt = blockIdx.y;
    int nb = ci * 64;

    // ---- load A halves (already bf16 in gmem) into swizzled smem ----
    #pragma unroll
    for (int it = 0; it < 8; it++) {
        int cid = t + it * 256;                 // 2048 16B chunks
        int r = cid >> 4, c = cid & 15;
        uint32_t dst = (uint32_t)(r * 256 + ((c ^ (r & 7)) << 4));
        int gi = (mt * 128 + r) * 16 + c;
        *(uint4*)(smc + AH_O + dst) = ((const uint4*)g_ah)[gi];
        *(uint4*)(smc + AL_O + dst) = ((const uint4*)g_al)[gi];
    }
    // ---- load B tile (queue fp32 -> bf16 hi/lo) ----
    #pragma unroll
    for (int it = 0; it < 8; it++) {
        int cid = t + it * 256;                 // 2048 float4s (64 x 32)
        int n = cid >> 5, c4 = cid & 31;
        float4 v = *(const float4*)(queue + (size_t)(nb + n) * D_ + c4 * 4);
        float vv[4] = {v.x, v.y, v.z, v.w};
        unsigned hp[4], lp[4];
        #pragma unroll
        for (int j = 0; j < 4; j++) {
            __nv_bfloat16 hb = __float2bfloat16_rn(vv[j]);
            float lo = vv[j] - __bfloat162float(hb);
            hp[j] = (unsigned)__bfloat16_as_ushort(hb);
            lp[j] = (unsigned)__bfloat16_as_ushort(__float2bfloat16_rn(lo));
        }
        int c = c4 >> 1;
        uint32_t dst = (uint32_t)(n * 256 + ((c ^ (n & 7)) << 4) + (c4 & 1) * 8);
        *(uint2*)(smc + BH_O + dst) = make_uint2(hp[0] | (hp[1] << 16), hp[2] | (hp[3] << 16));
        *(uint2*)(smc + BL_O + dst) = make_uint2(lp[0] | (lp[1] << 16), lp[2] | (lp[3] << 16));
    }
    __syncthreads();

    uint32_t ah = smem_u32(smc + AH_O), al = smem_u32(smc + AL_O);
    uint32_t bh = smem_u32(smc + BH_O), bl = smem_u32(smc + BL_O);

    float acc[4][2][4];
    #pragma unroll
    for (int mi = 0; mi < 4; mi++)
        #pragma unroll
        for (int ni = 0; ni < 2; ni++)
            #pragma unroll
            for (int j = 0; j < 4; j++) acc[mi][ni][j] = 0.f;

    int arow = wm * 64 + (lane & 15);           // +mi*16
    int brow = wn * 16 + (lane & 7);            // +ni*8
    int sx = lane & 7;

    #pragma unroll
    for (int ks = 0; ks < 8; ks++) {
        int kca = ks * 2 + (lane >> 4);
        int kcb = ks * 2 + ((lane >> 3) & 1);
        uint32_t Ah[4][4], Al[4][4], Bh[2][2], Bl[2][2];
        #pragma unroll
        for (int mi = 0; mi < 4; mi++) {
            uint32_t off = (uint32_t)((arow + mi * 16) * 256 + ((kca ^ sx) << 4));
            ldsm4(Ah[mi], ah + off);
            ldsm4(Al[mi], al + off);
        }
        #pragma unroll
        for (int ni = 0; ni < 2; ni++) {
            uint32_t off = (uint32_t)((brow + ni * 8) * 256 + ((kcb ^ sx) << 4));
            ldsm2(Bh[ni], bh + off);
            ldsm2(Bl[ni], bl + off);
        }
        #pragma unroll
        for (int mi = 0; mi < 4; mi++)
            #pragma unroll
            for (int ni = 0; ni < 2; ni++) {
                mma16816(acc[mi][ni], Ah[mi], Bh[ni]);
                mma16816(acc[mi][ni], Ah[mi], Bl[ni]);
                mma16816(acc[mi][ni], Al[mi], Bh[ni]);
            }
    }
    __syncthreads();                            // done reading A/B smem

    // ---- stage fragments (stride-66), then coalesced stores + cmax ----
    float* stage = (float*)smc;
    #pragma unroll
    for (int mi = 0; mi < 4; mi++)
        #pragma unroll
        for (int ni = 0; ni < 2; ni++) {
            int row = wm * 64 + mi * 16 + (lane >> 2);
            int col = wn * 16 + ni * 8 + (lane & 3) * 2;
            *(float2*)&stage[row * STG_W + col] =
                make_float2(acc[mi][ni][0] * INV_T, acc[mi][ni][1] * INV_T);
            *(float2*)&stage[(row + 8) * STG_W + col] =
                make_float2(acc[mi][ni][2] * INV_T, acc[mi][ni][3] * INV_T);
        }
    __syncthreads();

    #pragma unroll 2
    for (int rr = 0; rr < 16; rr++) {
        int row = w * 16 + rr;
        float v0 = stage[row * STG_W + lane];
        float v1 = stage[row * STG_W + 32 + lane];
        size_t gb = (size_t)(mt * 128 + row) * LD_ + 1 + nb;
        out[gb + lane]      = v0;
        out[gb + 32 + lane] = v1;
        float m0 = fmaxf(v0, v1);
        #pragma unroll
        for (int o = 16; o; o >>= 1)
            m0 = fmaxf(m0, __shfl_xor_sync(0xffffffffu, m0, o));
        if (lane == 0)
            g_cmax[(size_t)(mt * 128 + row) * NCHUNK + ci] = m0;
    }
}

// ---------------- k3: exact top-32 via chunk-max pruning -------------------
#define NBIN 8192
#define CCAP 1024
#define CHCAP 192

__global__ void __launch_bounds__(256)
k3_topk(const float* __restrict__ out) {
    __shared__ unsigned hist[NBIN];
    __shared__ unsigned long long cand[CCAP];
    __shared__ unsigned scnt[256];
    __shared__ int chlist[CHCAP];
    __shared__ unsigned s_tb, s_nch, s_nc;
    int t = threadIdx.x, lane = t & 31, w = t >> 5;
    int r = blockIdx.x;
    const float* row = out + (size_t)r * LD_ + 1;

    for (int i = t; i < NBIN; i += 256) hist[i] = 0;
    if (t == 0) { s_nch = 0; s_nc = 0; }
    __syncthreads();

    for (int i = t; i < NCHUNK; i += 256)
        atomicAdd(&hist[fkey(g_cmax[(size_t)r * NCHUNK + i]) >> 19], 1u);
    __syncthreads();

    {
        unsigned loc = 0;
        #pragma unroll 4
        for (int i = 0; i < 32; i++) loc += hist[t * 32 + i];
        scnt[t] = loc;
    }
    __syncthreads();

    if (t == 0) {
        unsigned cum = 0; int seg = 255;
        for (; seg >= 0; seg--) { cum += scnt[seg]; if (cum >= 32) break; }
        unsigned cum2 = cum - scnt[seg];
        int tb = seg * 32;
        for (int i = 31; i >= 0; i--) {
            cum2 += hist[seg * 32 + i];
            if (cum2 >= 32) { tb = seg * 32 + i; break; }
        }
        s_tb = (unsigned)tb;
    }
    __syncthreads();

    unsigned tb = s_tb;
    for (int i = t; i < NCHUNK; i += 256)
        if ((fkey(g_cmax[(size_t)r * NCHUNK + i]) >> 19) >= tb) {
            unsigned p = atomicAdd(&s_nch, 1u);
            if (p < CHCAP) chlist[p] = i;
        }
    __syncthreads();

    if (s_nch <= CHCAP) {
        int nch = (int)s_nch;
        for (int cidx = w; cidx < nch; cidx += 8) {
            int cbase = chlist[cidx] * 64;
            #pragma unroll
            for (int e = 0; e < 2; e++) {
                int j = cbase + lane * 2 + e;
                unsigned fk = fkey(row[j]);
                if ((fk >> 19) >= tb) {
                    unsigned p = atomicAdd(&s_nc, 1u);
                    if (p < CCAP)
                        cand[p] = ((unsigned long long)fk << 32) | (unsigned)(~(unsigned)j);
                }
            }
        }
    } else {
        for (int j = t; j < KQ; j += 256) {
            unsigned fk = fkey(row[j]);
            if ((fk >> 19) >= tb) {
                unsigned p = atomicAdd(&s_nc, 1u);
                if (p < CCAP)
                    cand[p] = ((unsigned long long)fk << 32) | (unsigned)(~(unsigned)j);
            }
        }
    }
    __syncthreads();
    int n = (int)min(s_nc, (unsigned)CCAP);

    // exact, order-independent rank-by-count (keys unique)
    for (int i = t; i < n; i += 256) {
        unsigned long long key = cand[i];
        int rank = 0;
        for (int j = 0; j < n; j++) rank += (cand[j] > key) ? 1 : 0;
        if (rank < 32) g_hard[r * 32 + rank] = (int)(~(unsigned)(key & 0xFFFFFFFFull));
    }
}

// ---------------- k4: mixed hard-negative logits ---------------------------
__global__ void k4_mix(const float* __restrict__ queue, const float* __restrict__ alpha,
                       const float* __restrict__ beta, const int* __restrict__ i1a,
                       const int* __restrict__ i1b, const int* __restrict__ i2,
                       float* __restrict__ out) {
    __shared__ float qsh[D_];
    __shared__ int hsh[32];
    int t = threadIdx.x, lane = t & 31, w = t >> 5;
    int r = blockIdx.x;
    if (t < D_) qsh[t] = g_outq[(size_t)r * D_ + t];
    if (t < 32) hsh[t] = g_hard[r * 32 + t];
    __syncthreads();
    float4 q4 = *(float4*)&qsh[lane * 4];

    #pragma unroll
    for (int e = 0; e < 2; e++) {
        int s = w * 2 + e;
        {
            int g1 = hsh[i1a[r * 16 + s]];
            int g2 = hsh[i1b[r * 16 + s]];
            float a = alpha[r * 16 + s];
            float4 n1 = *(const float4*)(queue + (size_t)g1 * D_ + lane * 4);
            float4 n2 = *(const float4*)(queue + (size_t)g2 * D_ + lane * 4);
            float4 v;
            v.x = a * n1.x + (1.f - a) * n2.x;
            v.y = a * n1.y + (1.f - a) * n2.y;
            v.z = a * n1.z + (1.f - a) * n2.z;
            v.w = a * n1.w + (1.f - a) * n2.w;
            float ss = v.x*v.x + v.y*v.y + v.z*v.z + v.w*v.w;
            float dq = v.x*q4.x + v.y*q4.y + v.z*q4.z + v.w*q4.w;
            #pragma unroll
            for (int o = 16; o; o >>= 1) {
                ss += __shfl_xor_sync(0xffffffffu, ss, o);
                dq += __shfl_xor_sync(0xffffffffu, dq, o);
            }
            if (lane == 0)
                out[(size_t)r * LD_ + 1 + KQ + s] = dq / fmaxf(sqrtf(ss), 1e-12f) * INV_T;
        }
        {
            int g = hsh[i2[r * 16 + s]];
            float bb = beta[r * 16 + s] * 0.5f;
            float4 n1 = *(const float4*)(queue + (size_t)g * D_ + lane * 4);
            float4 v;
            v.x = bb * q4.x + (1.f - bb) * n1.x;
            v.y = bb * q4.y + (1.f - bb) * n1.y;
            v.z = bb * q4.z + (1.f - bb) * n1.z;
            v.w = bb * q4.w + (1.f - bb) * n1.w;
            float ss = v.x*v.x + v.y*v.y + v.z*v.z + v.w*v.w;
            float dq = v.x*q4.x + v.y*q4.y + v.z*q4.z + v.w*q4.w;
            #pragma unroll
            for (int o = 16; o; o >>= 1) {
                ss += __shfl_xor_sync(0xffffffffu, ss, o);
                dq += __shfl_xor_sync(0xffffffffu, dq, o);
            }
            if (lane == 0)
                out[(size_t)r * LD_ + 1 + KQ + 16 + s] = dq / fmaxf(sqrtf(ss), 1e-12f) * INV_T;
        }
    }
}

// ---------------- tail: zero any region past logits ------------------------
__global__ void k_tail(float* __restrict__ out, int total) {
    for (int j = B_ * LD_ + blockIdx.x * blockDim.x + threadIdx.x; j < total;
         j += gridDim.x * blockDim.x)
        out[j] = 0.f;
}

// ---------------- launch ---------------------------------------------------
extern "C" void kernel_launch(void* const* d_in, const int* in_sizes, int n_in,
                              void* d_out, int out_size) {
    const float* q     = (const float*)d_in[0];
    const float* k     = (const float*)d_in[1];
    const float* Wq    = (const float*)d_in[2];
    const float* Wk    = (const float*)d_in[3];
    const float* queue = (const float*)d_in[4];
    const float* alpha = (const float*)d_in[5];
    const float* beta  = (const float*)d_in[6];
    const int*   i1a   = (const int*)d_in[7];
    const int*   i1b   = (const int*)d_in[8];
    const int*   i2    = (const int*)d_in[9];
    float* out = (float*)d_out;

    cudaFuncSetAttribute(k2m_gemm, cudaFuncAttributeMaxDynamicSharedMemorySize, K2M_SMEM);

    k1_gemm<<<dim3(16, SPLITK), 256>>>(q, k, Wq, Wk);
    k1b_norm<<<8, 256>>>(out);
    k2m_gemm<<<dim3(1024, 2), 256, K2M_SMEM>>>(queue, out);
    k3_topk<<<256, 256>>>(out);
    k4_mix<<<256, 256>>>(queue, alpha, beta, i1a, i1b, i2, out);
    if (out_size > B_ * LD_) k_tail<<<1, 256>>>(out, out_size);
}